// round 1
// baseline (speedup 1.0000x reference)
#include <cuda_runtime.h>
#include <cstdint>

#define NN 10000
#define EE 160000
#define EP 170000      // E + N self loops
#define DIN 4096
#define DH 256
#define HEADS 4
#define OUTC 228       // 128 + 100

// ---------------- scratch (static device globals; no allocs) ----------------
__device__ float g_hidden[NN * DH];        // 10.24 MB
__device__ float g_xl[NN * 512];           // 20.5 MB (max H*C = 512)
__device__ float g_xr[NN * 512];           // 20.5 MB
__device__ float g_logits[EP * HEADS];     // 2.7 MB (reused as exp(p) in place)
__device__ int   g_cnt[NN];
__device__ int   g_row[NN + 1];
__device__ int   g_cur[NN];
__device__ int   g_eids[EP];

// ---------------- CSR build ----------------
__global__ void k_zero_cnt() {
    int i = blockIdx.x * blockDim.x + threadIdx.x;
    if (i < NN) g_cnt[i] = 0;
}

__global__ void k_hist(const int* __restrict__ ei) {
    int e = blockIdx.x * blockDim.x + threadIdx.x;
    if (e >= EP) return;
    int dst = (e < EE) ? ei[EE + e] : (e - EE);
    atomicAdd(&g_cnt[dst], 1);
}

__global__ void k_scan() {
    __shared__ int sh[1024];
    __shared__ int s_off;
    int tid = threadIdx.x;
    if (tid == 0) s_off = 0;
    __syncthreads();
    for (int base = 0; base < NN; base += 1024) {
        int v = (base + tid < NN) ? g_cnt[base + tid] : 0;
        sh[tid] = v;
        __syncthreads();
        for (int d = 1; d < 1024; d <<= 1) {
            int t = (tid >= d) ? sh[tid - d] : 0;
            __syncthreads();
            sh[tid] += t;
            __syncthreads();
        }
        int incl = sh[tid];
        int tot  = sh[1023];
        int off  = s_off;
        __syncthreads();
        if (base + tid < NN) {
            int excl = off + incl - v;
            g_row[base + tid] = excl;
            g_cur[base + tid] = excl;
        }
        if (tid == 0) s_off = off + tot;
        __syncthreads();
    }
    if (tid == 0) g_row[NN] = s_off;
}

__global__ void k_scatter(const int* __restrict__ ei) {
    int e = blockIdx.x * blockDim.x + threadIdx.x;
    if (e >= EP) return;
    int dst = (e < EE) ? ei[EE + e] : (e - EE);
    int pos = atomicAdd(&g_cur[dst], 1);
    g_eids[pos] = e;
}

// ---------------- SGEMM: C[M,N] = A[M,K] @ B[K,N] (+bias, +relu) ----------------
template <int RELU>
__global__ void __launch_bounds__(256)
sgemm_kernel(const float* __restrict__ A, const float* __restrict__ B,
             const float* __restrict__ bias, float* __restrict__ C,
             int M, int N, int K) {
    __shared__ float As[16][132];
    __shared__ float Bs[16][132];

    int m0 = blockIdx.y * 128;
    int n0 = blockIdx.x * 128;
    int tid = threadIdx.x;
    int tx = tid % 16, ty = tid / 16;

    float acc[8][8];
#pragma unroll
    for (int i = 0; i < 8; i++)
#pragma unroll
        for (int j = 0; j < 8; j++) acc[i][j] = 0.f;

    int arow = tid / 4;          // 0..63
    int acol = (tid % 4) * 4;    // 0,4,8,12
    int brow = tid / 32;         // 0..7
    int bcol = (tid % 32) * 4;   // 0..124

    for (int k0 = 0; k0 < K; k0 += 16) {
#pragma unroll
        for (int r = 0; r < 2; ++r) {
            int row = arow + r * 64;
            float4 v = make_float4(0.f, 0.f, 0.f, 0.f);
            if (m0 + row < M)
                v = *(const float4*)(A + (size_t)(m0 + row) * K + k0 + acol);
            As[acol + 0][row] = v.x;
            As[acol + 1][row] = v.y;
            As[acol + 2][row] = v.z;
            As[acol + 3][row] = v.w;
        }
#pragma unroll
        for (int r = 0; r < 2; ++r) {
            int krow = brow + r * 8;
            int col = n0 + bcol;
            float4 v;
            if (col + 3 < N) {
                v = *(const float4*)(B + (size_t)(k0 + krow) * N + col);
            } else {
                v.x = (col + 0 < N) ? B[(size_t)(k0 + krow) * N + col + 0] : 0.f;
                v.y = (col + 1 < N) ? B[(size_t)(k0 + krow) * N + col + 1] : 0.f;
                v.z = (col + 2 < N) ? B[(size_t)(k0 + krow) * N + col + 2] : 0.f;
                v.w = (col + 3 < N) ? B[(size_t)(k0 + krow) * N + col + 3] : 0.f;
            }
            Bs[krow][bcol + 0] = v.x;
            Bs[krow][bcol + 1] = v.y;
            Bs[krow][bcol + 2] = v.z;
            Bs[krow][bcol + 3] = v.w;
        }
        __syncthreads();
#pragma unroll
        for (int kk = 0; kk < 16; ++kk) {
            float4 a0 = *(const float4*)&As[kk][ty * 8];
            float4 a1 = *(const float4*)&As[kk][ty * 8 + 4];
            float4 b0 = *(const float4*)&Bs[kk][tx * 8];
            float4 b1 = *(const float4*)&Bs[kk][tx * 8 + 4];
            float a[8] = {a0.x, a0.y, a0.z, a0.w, a1.x, a1.y, a1.z, a1.w};
            float b[8] = {b0.x, b0.y, b0.z, b0.w, b1.x, b1.y, b1.z, b1.w};
#pragma unroll
            for (int i = 0; i < 8; i++)
#pragma unroll
                for (int j = 0; j < 8; j++) acc[i][j] += a[i] * b[j];
        }
        __syncthreads();
    }

#pragma unroll
    for (int i = 0; i < 8; i++) {
        int row = m0 + ty * 8 + i;
        if (row >= M) continue;
#pragma unroll
        for (int j = 0; j < 8; j++) {
            int col = n0 + tx * 8 + j;
            if (col >= N) continue;
            float v = acc[i][j];
            if (bias) v += bias[col];
            if (RELU) v = fmaxf(v, 0.f);
            C[(size_t)row * N + col] = v;
        }
    }
}

// ---------------- per-edge GATv2 logits (one warp per edge) ----------------
__global__ void k_logits(const int* __restrict__ ei, const float* __restrict__ att,
                         int HC, int C) {
    int wid = (blockIdx.x * blockDim.x + threadIdx.x) >> 5;
    int lane = threadIdx.x & 31;
    if (wid >= EP) return;
    int e = wid;
    int src = (e < EE) ? ei[e] : (e - EE);
    int dst = (e < EE) ? ei[EE + e] : (e - EE);
    const float* xl = g_xl + (size_t)src * HC;
    const float* xr = g_xr + (size_t)dst * HC;
    float p0 = 0.f, p1 = 0.f, p2 = 0.f, p3 = 0.f;
    for (int c = lane; c < HC; c += 32) {
        float v = xl[c] + xr[c];
        v = (v > 0.f) ? v : 0.2f * v;
        float t = v * att[c];
        int h = c / C;
        if (h == 0) p0 += t;
        else if (h == 1) p1 += t;
        else if (h == 2) p2 += t;
        else p3 += t;
    }
#pragma unroll
    for (int off = 16; off; off >>= 1) {
        p0 += __shfl_xor_sync(0xffffffffu, p0, off);
        p1 += __shfl_xor_sync(0xffffffffu, p1, off);
        p2 += __shfl_xor_sync(0xffffffffu, p2, off);
        p3 += __shfl_xor_sync(0xffffffffu, p3, off);
    }
    if (lane == 0) {
        float4 r = make_float4(p0, p1, p2, p3);
        *(float4*)(g_logits + (size_t)e * 4) = r;
    }
}

__device__ __forceinline__ float pick4(float4 p, int h) {
    return h == 0 ? p.x : (h == 1 ? p.y : (h == 2 ? p.z : p.w));
}

// ---------------- per-dst softmax + aggregation (one 128-thread block per dst) ----------------
__global__ void __launch_bounds__(128)
k_agg(const int* __restrict__ ei, const float* __restrict__ bias,
      float* __restrict__ out, int HC, int C, int col_off) {
    int i = blockIdx.x;
    int tid = threadIdx.x;
    int start = g_row[i];
    int end   = g_row[i + 1];

    __shared__ float s_dinv[HEADS];
    __shared__ float sacc[512];

    // Phase A (warp 0): max + exp-in-place + denom
    if (tid < 32) {
        float m0 = -1e30f, m1 = -1e30f, m2 = -1e30f, m3 = -1e30f;
        for (int t = start + tid; t < end; t += 32) {
            int e = g_eids[t];
            float4 l = *(const float4*)(g_logits + (size_t)e * 4);
            m0 = fmaxf(m0, l.x); m1 = fmaxf(m1, l.y);
            m2 = fmaxf(m2, l.z); m3 = fmaxf(m3, l.w);
        }
#pragma unroll
        for (int off = 16; off; off >>= 1) {
            m0 = fmaxf(m0, __shfl_xor_sync(0xffffffffu, m0, off));
            m1 = fmaxf(m1, __shfl_xor_sync(0xffffffffu, m1, off));
            m2 = fmaxf(m2, __shfl_xor_sync(0xffffffffu, m2, off));
            m3 = fmaxf(m3, __shfl_xor_sync(0xffffffffu, m3, off));
        }
        float s0 = 0.f, s1 = 0.f, s2 = 0.f, s3 = 0.f;
        for (int t = start + tid; t < end; t += 32) {
            int e = g_eids[t];
            float4 l = *(const float4*)(g_logits + (size_t)e * 4);
            float4 p;
            p.x = __expf(l.x - m0); p.y = __expf(l.y - m1);
            p.z = __expf(l.z - m2); p.w = __expf(l.w - m3);
            *(float4*)(g_logits + (size_t)e * 4) = p;
            s0 += p.x; s1 += p.y; s2 += p.z; s3 += p.w;
        }
#pragma unroll
        for (int off = 16; off; off >>= 1) {
            s0 += __shfl_xor_sync(0xffffffffu, s0, off);
            s1 += __shfl_xor_sync(0xffffffffu, s1, off);
            s2 += __shfl_xor_sync(0xffffffffu, s2, off);
            s3 += __shfl_xor_sync(0xffffffffu, s3, off);
        }
        if (tid == 0) {
            s_dinv[0] = 1.f / s0; s_dinv[1] = 1.f / s1;
            s_dinv[2] = 1.f / s2; s_dinv[3] = 1.f / s3;
        }
    }
    __syncthreads();

    // Phase B: channel-parallel weighted aggregation
    int c0 = tid, c1 = tid + 128, c2 = tid + 256, c3 = tid + 384;
    bool v3 = c3 < HC;                      // c0..c2 always < 400 <= HC
    int h0 = c0 / C, h1 = c1 / C, h2 = c2 / C, h3 = v3 ? (c3 / C) : 0;
    float d0 = s_dinv[h0], d1 = s_dinv[h1], d2 = s_dinv[h2], d3 = s_dinv[h3];

    float a0 = 0.f, a1 = 0.f, a2 = 0.f, a3 = 0.f;
    for (int t = start; t < end; ++t) {
        int e = g_eids[t];
        int src = (e < EE) ? ei[e] : (e - EE);
        const float* row = g_xl + (size_t)src * HC;
        float4 p = *(const float4*)(g_logits + (size_t)e * 4);
        float w0 = pick4(p, h0) * d0;
        float w1 = pick4(p, h1) * d1;
        float w2 = pick4(p, h2) * d2;
        float w3 = pick4(p, h3) * d3;
        a0 += w0 * row[c0];
        a1 += w1 * row[c1];
        a2 += w2 * row[c2];
        if (v3) a3 += w3 * row[c3];
    }
    sacc[c0] = a0;
    sacc[c1] = a1;
    sacc[c2] = a2;
    if (v3) sacc[c3] = a3;
    __syncthreads();

    // epilogue: mean over heads + bias
    for (int cc = tid; cc < C; cc += 128) {
        float s = 0.f;
#pragma unroll
        for (int h = 0; h < HEADS; ++h) s += sacc[h * C + cc];
        out[(size_t)i * OUTC + col_off + cc] = s * 0.25f + bias[cc];
    }
}

// ---------------- launcher ----------------
extern "C" void kernel_launch(void* const* d_in, const int* in_sizes, int n_in,
                              void* d_out, int out_size) {
    (void)in_sizes; (void)n_in; (void)out_size;
    const float* x    = (const float*)d_in[0];
    const float* fc_w = (const float*)d_in[1];
    const float* fc_b = (const float*)d_in[2];
    const int*   ei   = (const int*)d_in[19];
    float* out = (float*)d_out;

    float *hidden, *xl, *xr;
    cudaGetSymbolAddress((void**)&hidden, g_hidden);
    cudaGetSymbolAddress((void**)&xl, g_xl);
    cudaGetSymbolAddress((void**)&xr, g_xr);

    // CSR build
    k_zero_cnt<<<(NN + 255) / 256, 256>>>();
    k_hist<<<(EP + 255) / 256, 256>>>(ei);
    k_scan<<<1, 1024>>>();
    k_scatter<<<(EP + 255) / 256, 256>>>(ei);

    // hidden = relu(x @ fc_w + fc_b)
    dim3 g1(DH / 128, (NN + 127) / 128);
    sgemm_kernel<1><<<g1, 256>>>(x, fc_w, fc_b, hidden, NN, DH, DIN);

    struct Conv { int wl, wr, att, b, C; size_t out_base; int col; };
    const Conv convs[4] = {
        { 3,  4,  5,  6, 128, 0,                  0   },   // mu
        { 7,  8,  9, 10, 128, (size_t)NN * OUTC,  0   },   // logstd
        {11, 12, 13, 14, 100, 0,                  128 },   // addon mu
        {15, 16, 17, 18, 100, (size_t)NN * OUTC,  128 },   // addon logstd
    };

    for (int cv = 0; cv < 4; ++cv) {
        const Conv c = convs[cv];
        int HC = HEADS * c.C;
        dim3 gg((HC + 127) / 128, (NN + 127) / 128);
        sgemm_kernel<0><<<gg, 256>>>(hidden, (const float*)d_in[c.wl], nullptr, xl, NN, HC, DH);
        sgemm_kernel<0><<<gg, 256>>>(hidden, (const float*)d_in[c.wr], nullptr, xr, NN, HC, DH);
        k_logits<<<(EP * 32 + 255) / 256, 256>>>(ei, (const float*)d_in[c.att], HC, c.C);
        k_agg<<<NN, 128>>>(ei, (const float*)d_in[c.b], out + c.out_base, HC, c.C, c.col);
    }
}

// round 3
// speedup vs baseline: 1.4268x; 1.4268x over previous
#include <cuda_runtime.h>
#include <cstdint>

#define NN 10000
#define EE 160000
#define EP 170000      // E + N self loops
#define DIN 4096
#define DH 256
#define HEADS 4
#define OUTC 228       // 128 + 100

// ---------------- scratch (static device globals; no allocs) ----------------
__device__ float g_hidden[NN * DH];        // 10.24 MB
__device__ float g_xl[NN * 512];           // 20.5 MB (max H*C = 512)
__device__ float g_xr[NN * 512];           // 20.5 MB
__device__ float g_logits[EP * HEADS];     // 2.7 MB (reused as exp(p) in place)
__device__ int   g_cnt[NN];
__device__ int   g_row[NN + 1];
__device__ int   g_cur[NN];
__device__ int   g_eids[EP];

// ---------------- CSR build ----------------
__global__ void k_zero_cnt() {
    int i = blockIdx.x * blockDim.x + threadIdx.x;
    if (i < NN) g_cnt[i] = 0;
}

__global__ void k_hist(const int* __restrict__ ei) {
    int e = blockIdx.x * blockDim.x + threadIdx.x;
    if (e >= EP) return;
    int dst = (e < EE) ? ei[EE + e] : (e - EE);
    atomicAdd(&g_cnt[dst], 1);
}

__global__ void k_scan() {
    __shared__ int sh[1024];
    __shared__ int s_off;
    int tid = threadIdx.x;
    if (tid == 0) s_off = 0;
    __syncthreads();
    for (int base = 0; base < NN; base += 1024) {
        int v = (base + tid < NN) ? g_cnt[base + tid] : 0;
        sh[tid] = v;
        __syncthreads();
        for (int d = 1; d < 1024; d <<= 1) {
            int t = (tid >= d) ? sh[tid - d] : 0;
            __syncthreads();
            sh[tid] += t;
            __syncthreads();
        }
        int incl = sh[tid];
        int tot  = sh[1023];
        int off  = s_off;
        __syncthreads();
        if (base + tid < NN) {
            int excl = off + incl - v;
            g_row[base + tid] = excl;
            g_cur[base + tid] = excl;
        }
        if (tid == 0) s_off = off + tot;
        __syncthreads();
    }
    if (tid == 0) g_row[NN] = s_off;
}

__global__ void k_scatter(const int* __restrict__ ei) {
    int e = blockIdx.x * blockDim.x + threadIdx.x;
    if (e >= EP) return;
    int dst = (e < EE) ? ei[EE + e] : (e - EE);
    int pos = atomicAdd(&g_cur[dst], 1);
    g_eids[pos] = e;
}

// =================== 3xTF32 tensor-core GEMM ===================
// C[M,N] = A[M,K] @ B[K,N] (+bias, +relu).  Requires K % 16 == 0, N % 4 == 0.
#define BM 128
#define BN 128
#define BK 16
#define A_STRIDE 20    // floats; 128x20 -> conflict-free a-frag LDS, 80B row = 16B aligned
#define B_STRIDE 136   // floats; 16x136 -> conflict-free b-frag LDS, 544B row = 16B aligned

__device__ __forceinline__ void tf32_split(float f, uint32_t& hi, uint32_t& lo) {
    asm("cvt.rna.tf32.f32 %0, %1;" : "=r"(hi) : "f"(f));
    float d = f - __uint_as_float(hi);
    asm("cvt.rna.tf32.f32 %0, %1;" : "=r"(lo) : "f"(d));
}

#define MMA_TF32(c, a, b)                                                       \
    asm volatile(                                                               \
        "mma.sync.aligned.m16n8k8.row.col.f32.tf32.tf32.f32 "                   \
        "{%0,%1,%2,%3}, {%4,%5,%6,%7}, {%8,%9}, {%0,%1,%2,%3};"                 \
        : "+f"((c)[0]), "+f"((c)[1]), "+f"((c)[2]), "+f"((c)[3])                \
        : "r"((a)[0]), "r"((a)[1]), "r"((a)[2]), "r"((a)[3]),                   \
          "r"((b)[0]), "r"((b)[1]))

__device__ __forceinline__ void cp_async16(uint32_t smem, const void* gmem, int valid_bytes) {
    asm volatile("cp.async.cg.shared.global [%0], [%1], 16, %2;\n"
                 :: "r"(smem), "l"(gmem), "r"(valid_bytes));
}

template <int RELU>
__global__ void __launch_bounds__(256)
mma_gemm(const float* __restrict__ A, const float* __restrict__ B,
         const float* __restrict__ bias, float* __restrict__ C,
         int M, int N, int K) {
    __shared__ float As[2][BM][A_STRIDE];
    __shared__ float Bs[2][BK][B_STRIDE];

    const int tid = threadIdx.x;
    const int wid = tid >> 5;
    const int lane = tid & 31;
    const int warp_m = wid >> 2;        // 0..1  -> 64-row slab
    const int warp_n = wid & 3;         // 0..3  -> 32-col slab
    const int m0 = blockIdx.y * BM;
    const int n0 = blockIdx.x * BN;

    const uint32_t sA = (uint32_t)__cvta_generic_to_shared(&As[0][0][0]);
    const uint32_t sB = (uint32_t)__cvta_generic_to_shared(&Bs[0][0][0]);

    float acc[4][4][4];
#pragma unroll
    for (int i = 0; i < 4; i++)
#pragma unroll
        for (int j = 0; j < 4; j++)
#pragma unroll
            for (int k = 0; k < 4; k++) acc[i][j][k] = 0.f;

    const int KT = K / BK;

    // ---- async stage loader ----
    auto load_stage = [&](int kt, int s) {
        const uint32_t baseA = sA + (uint32_t)s * (BM * A_STRIDE * 4);
        const uint32_t baseB = sB + (uint32_t)s * (BK * B_STRIDE * 4);
#pragma unroll
        for (int i = 0; i < 2; i++) {
            int f4 = tid + i * 256;                 // 0..511
            int row = f4 >> 2, c4 = f4 & 3;         // A tile: 128 rows x 4 f4/row
            const float* src = A + (size_t)(m0 + row) * K + kt * BK + c4 * 4;
            int v = (m0 + row < M) ? 16 : 0;
            cp_async16(baseA + (uint32_t)(row * A_STRIDE + c4 * 4) * 4, src, v);
        }
#pragma unroll
        for (int i = 0; i < 2; i++) {
            int f4 = tid + i * 256;
            int row = f4 >> 5, c4 = f4 & 31;        // B tile: 16 rows x 32 f4/row
            int col = c4 * 4;
            const float* src = B + (size_t)(kt * BK + row) * N + n0 + col;
            int v = (n0 + col < N) ? 16 : 0;
            cp_async16(baseB + (uint32_t)(row * B_STRIDE + col) * 4, src, v);
        }
    };

    load_stage(0, 0);
    asm volatile("cp.async.commit_group;\n");

    const int r4 = lane >> 2;       // 0..7
    const int c4l = lane & 3;       // 0..3

    for (int kt = 0; kt < KT; ++kt) {
        if (kt + 1 < KT) load_stage(kt + 1, (kt + 1) & 1);
        asm volatile("cp.async.commit_group;\n");
        asm volatile("cp.async.wait_group 1;\n");
        __syncthreads();

        const int s = kt & 1;
#pragma unroll
        for (int kk = 0; kk < BK; kk += 8) {
            uint32_t ah[4][4], al[4][4], bh[4][2], bl[4][2];
#pragma unroll
            for (int mi = 0; mi < 4; ++mi) {
                int rb = warp_m * 64 + mi * 16;
                float f0 = As[s][rb + r4][kk + c4l];
                float f1 = As[s][rb + r4 + 8][kk + c4l];
                float f2 = As[s][rb + r4][kk + c4l + 4];
                float f3 = As[s][rb + r4 + 8][kk + c4l + 4];
                tf32_split(f0, ah[mi][0], al[mi][0]);
                tf32_split(f1, ah[mi][1], al[mi][1]);
                tf32_split(f2, ah[mi][2], al[mi][2]);
                tf32_split(f3, ah[mi][3], al[mi][3]);
            }
#pragma unroll
            for (int ni = 0; ni < 4; ++ni) {
                int cb = warp_n * 32 + ni * 8 + r4;
                float f0 = Bs[s][kk + c4l][cb];
                float f1 = Bs[s][kk + c4l + 4][cb];
                tf32_split(f0, bh[ni][0], bl[ni][0]);
                tf32_split(f1, bh[ni][1], bl[ni][1]);
            }
#pragma unroll
            for (int mi = 0; mi < 4; ++mi)
#pragma unroll
                for (int ni = 0; ni < 4; ++ni) {
                    MMA_TF32(acc[mi][ni], ah[mi], bh[ni]);
                    MMA_TF32(acc[mi][ni], al[mi], bh[ni]);
                    MMA_TF32(acc[mi][ni], ah[mi], bl[ni]);
                }
        }
        __syncthreads();
    }

    // ---- epilogue ----
    const int cc2 = (lane & 3) * 2;
#pragma unroll
    for (int mi = 0; mi < 4; ++mi) {
        int row0 = m0 + warp_m * 64 + mi * 16 + r4;
        int row1 = row0 + 8;
#pragma unroll
        for (int ni = 0; ni < 4; ++ni) {
            int col = n0 + warp_n * 32 + ni * 8 + cc2;
            if (col >= N) continue;            // N even -> col+1 also valid when col<N
            float b0 = bias ? bias[col] : 0.f;
            float b1 = bias ? bias[col + 1] : 0.f;
            if (row0 < M) {
                float v0 = acc[mi][ni][0] + b0;
                float v1 = acc[mi][ni][1] + b1;
                if (RELU) { v0 = fmaxf(v0, 0.f); v1 = fmaxf(v1, 0.f); }
                *(float2*)(C + (size_t)row0 * N + col) = make_float2(v0, v1);
            }
            if (row1 < M) {
                float v0 = acc[mi][ni][2] + b0;
                float v1 = acc[mi][ni][3] + b1;
                if (RELU) { v0 = fmaxf(v0, 0.f); v1 = fmaxf(v1, 0.f); }
                *(float2*)(C + (size_t)row1 * N + col) = make_float2(v0, v1);
            }
        }
    }
}

// ---------------- per-edge GATv2 logits (one warp per edge, float4) ----------------
__global__ void k_logits(const int* __restrict__ ei, const float* __restrict__ att,
                         int HC, int C) {
    int wid = (blockIdx.x * blockDim.x + threadIdx.x) >> 5;
    int lane = threadIdx.x & 31;
    if (wid >= EP) return;
    int e = wid;
    int src = (e < EE) ? ei[e] : (e - EE);
    int dst = (e < EE) ? ei[EE + e] : (e - EE);
    const float4* xl = (const float4*)(g_xl + (size_t)src * HC);
    const float4* xr = (const float4*)(g_xr + (size_t)dst * HC);
    const float4* at = (const float4*)att;
    int nf4 = HC >> 2;
    float p0 = 0.f, p1 = 0.f, p2 = 0.f, p3 = 0.f;
    for (int c4 = lane; c4 < nf4; c4 += 32) {
        float4 l = xl[c4], r = xr[c4], a = at[c4];
        float vx = l.x + r.x; vx = (vx > 0.f) ? vx : 0.2f * vx;
        float vy = l.y + r.y; vy = (vy > 0.f) ? vy : 0.2f * vy;
        float vz = l.z + r.z; vz = (vz > 0.f) ? vz : 0.2f * vz;
        float vw = l.w + r.w; vw = (vw > 0.f) ? vw : 0.2f * vw;
        float t = vx * a.x + vy * a.y + vz * a.z + vw * a.w;
        int h = (c4 * 4) / C;          // head boundaries (100/128) are 4-aligned
        if (h == 0) p0 += t;
        else if (h == 1) p1 += t;
        else if (h == 2) p2 += t;
        else p3 += t;
    }
#pragma unroll
    for (int off = 16; off; off >>= 1) {
        p0 += __shfl_xor_sync(0xffffffffu, p0, off);
        p1 += __shfl_xor_sync(0xffffffffu, p1, off);
        p2 += __shfl_xor_sync(0xffffffffu, p2, off);
        p3 += __shfl_xor_sync(0xffffffffu, p3, off);
    }
    if (lane == 0) {
        float4 r = make_float4(p0, p1, p2, p3);
        *(float4*)(g_logits + (size_t)e * 4) = r;
    }
}

__device__ __forceinline__ float pick4(float4 p, int h) {
    return h == 0 ? p.x : (h == 1 ? p.y : (h == 2 ? p.z : p.w));
}

// ---------------- per-dst softmax + aggregation (one 128-thread block per dst) ----------------
__global__ void __launch_bounds__(128)
k_agg(const int* __restrict__ ei, const float* __restrict__ bias,
      float* __restrict__ out, int HC, int C, int col_off) {
    int i = blockIdx.x;
    int tid = threadIdx.x;
    int start = g_row[i];
    int end   = g_row[i + 1];

    __shared__ float s_dinv[HEADS];
    __shared__ float sacc[512];

    // Phase A (warp 0): max + exp-in-place + denom
    if (tid < 32) {
        float m0 = -1e30f, m1 = -1e30f, m2 = -1e30f, m3 = -1e30f;
        for (int t = start + tid; t < end; t += 32) {
            int e = g_eids[t];
            float4 l = *(const float4*)(g_logits + (size_t)e * 4);
            m0 = fmaxf(m0, l.x); m1 = fmaxf(m1, l.y);
            m2 = fmaxf(m2, l.z); m3 = fmaxf(m3, l.w);
        }
#pragma unroll
        for (int off = 16; off; off >>= 1) {
            m0 = fmaxf(m0, __shfl_xor_sync(0xffffffffu, m0, off));
            m1 = fmaxf(m1, __shfl_xor_sync(0xffffffffu, m1, off));
            m2 = fmaxf(m2, __shfl_xor_sync(0xffffffffu, m2, off));
            m3 = fmaxf(m3, __shfl_xor_sync(0xffffffffu, m3, off));
        }
        float s0 = 0.f, s1 = 0.f, s2 = 0.f, s3 = 0.f;
        for (int t = start + tid; t < end; t += 32) {
            int e = g_eids[t];
            float4 l = *(const float4*)(g_logits + (size_t)e * 4);
            float4 p;
            p.x = __expf(l.x - m0); p.y = __expf(l.y - m1);
            p.z = __expf(l.z - m2); p.w = __expf(l.w - m3);
            *(float4*)(g_logits + (size_t)e * 4) = p;
            s0 += p.x; s1 += p.y; s2 += p.z; s3 += p.w;
        }
#pragma unroll
        for (int off = 16; off; off >>= 1) {
            s0 += __shfl_xor_sync(0xffffffffu, s0, off);
            s1 += __shfl_xor_sync(0xffffffffu, s1, off);
            s2 += __shfl_xor_sync(0xffffffffu, s2, off);
            s3 += __shfl_xor_sync(0xffffffffu, s3, off);
        }
        if (tid == 0) {
            s_dinv[0] = 1.f / s0; s_dinv[1] = 1.f / s1;
            s_dinv[2] = 1.f / s2; s_dinv[3] = 1.f / s3;
        }
    }
    __syncthreads();

    // Phase B: channel-parallel weighted aggregation
    int c0 = tid, c1 = tid + 128, c2 = tid + 256, c3 = tid + 384;
    bool v3 = c3 < HC;                      // c0..c2 always < 400 <= HC
    int h0 = c0 / C, h1 = c1 / C, h2 = c2 / C, h3 = v3 ? (c3 / C) : 0;
    float d0 = s_dinv[h0], d1 = s_dinv[h1], d2 = s_dinv[h2], d3 = s_dinv[h3];

    float a0 = 0.f, a1 = 0.f, a2 = 0.f, a3 = 0.f;
    for (int t = start; t < end; ++t) {
        int e = g_eids[t];
        int src = (e < EE) ? ei[e] : (e - EE);
        const float* row = g_xl + (size_t)src * HC;
        float4 p = *(const float4*)(g_logits + (size_t)e * 4);
        float w0 = pick4(p, h0) * d0;
        float w1 = pick4(p, h1) * d1;
        float w2 = pick4(p, h2) * d2;
        float w3 = pick4(p, h3) * d3;
        a0 += w0 * row[c0];
        a1 += w1 * row[c1];
        a2 += w2 * row[c2];
        if (v3) a3 += w3 * row[c3];
    }
    sacc[c0] = a0;
    sacc[c1] = a1;
    sacc[c2] = a2;
    if (v3) sacc[c3] = a3;
    __syncthreads();

    // epilogue: mean over heads + bias
    for (int cc = tid; cc < C; cc += 128) {
        float s = 0.f;
#pragma unroll
        for (int h = 0; h < HEADS; ++h) s += sacc[h * C + cc];
        out[(size_t)i * OUTC + col_off + cc] = s * 0.25f + bias[cc];
    }
}

// ---------------- launcher ----------------
extern "C" void kernel_launch(void* const* d_in, const int* in_sizes, int n_in,
                              void* d_out, int out_size) {
    (void)in_sizes; (void)n_in; (void)out_size;
    const float* x    = (const float*)d_in[0];
    const float* fc_w = (const float*)d_in[1];
    const float* fc_b = (const float*)d_in[2];
    const int*   ei   = (const int*)d_in[19];
    float* out = (float*)d_out;

    float *hidden, *xl, *xr;
    cudaGetSymbolAddress((void**)&hidden, g_hidden);
    cudaGetSymbolAddress((void**)&xl, g_xl);
    cudaGetSymbolAddress((void**)&xr, g_xr);

    // CSR build
    k_zero_cnt<<<(NN + 255) / 256, 256>>>();
    k_hist<<<(EP + 255) / 256, 256>>>(ei);
    k_scan<<<1, 1024>>>();
    k_scatter<<<(EP + 255) / 256, 256>>>(ei);

    // hidden = relu(x @ fc_w + fc_b)
    dim3 g1((DH + 127) / 128, (NN + 127) / 128);
    mma_gemm<1><<<g1, 256>>>(x, fc_w, fc_b, hidden, NN, DH, DIN);

    struct Conv { int wl, wr, att, b, C; size_t out_base; int col; };
    const Conv convs[4] = {
        { 3,  4,  5,  6, 128, 0,                  0   },   // mu
        { 7,  8,  9, 10, 128, (size_t)NN * OUTC,  0   },   // logstd
        {11, 12, 13, 14, 100, 0,                  128 },   // addon mu
        {15, 16, 17, 18, 100, (size_t)NN * OUTC,  128 },   // addon logstd
    };

    for (int cv = 0; cv < 4; ++cv) {
        const Conv c = convs[cv];
        int HC = HEADS * c.C;
        dim3 gg((HC + 127) / 128, (NN + 127) / 128);
        mma_gemm<0><<<gg, 256>>>(hidden, (const float*)d_in[c.wl], nullptr, xl, NN, HC, DH);
        mma_gemm<0><<<gg, 256>>>(hidden, (const float*)d_in[c.wr], nullptr, xr, NN, HC, DH);
        k_logits<<<(EP * 32 + 255) / 256, 256>>>(ei, (const float*)d_in[c.att], HC, c.C);
        k_agg<<<NN, 128>>>(ei, (const float*)d_in[c.b], out + c.out_base, HC, c.C, c.col);
    }
}